// round 14
// baseline (speedup 1.0000x reference)
#include <cuda_runtime.h>
#include <cstdint>

// Per-row nonlinear scan, w[k+1] = w[k] + a/w[k] - b*x[k], 32768 rows x 1024.
//
// ARITHMETIC (FROZEN): w = w + a / w - b * xv; xv from smem, w to smem —
// bitwise-identical to reference (rel_err 0.0 in R1/R2/R11/R13). Closed
// lines: rcp.approx (R3: 2.05), manual Markstein (R5/R9: slower), altered
// tail (R8: 9e-2), in-warp store fusion (R6/R7), xv reg-preload (R10:
// neutral), TILE=128 (R12: I$ blowout).
//
// STRUCTURE = R13 (warp specialization, best: 52.5us ncu) + ONE change:
// block-wide __syncthreads() -> per-pair NAMED barriers. Compute warp cw
// syncs only with the DMA warp (bar.sync 1+cw, 64); the two compute chains
// decouple so per-warp jitter no longer max-combines at every tile boundary.

#define N_COLS 1024
#define TILE 64
#define NT (N_COLS / TILE)   // 16
#define CW 2                 // compute warps per block
#define THREADS ((CW + 1) * 32)

#define PAIR_BAR(id) asm volatile("bar.sync %0, %1;" :: "r"(id), "r"(64) : "memory")

__global__ __launch_bounds__(THREADS, 4)
void DDK_77644418777662_kernel(const float* __restrict__ x,
                               const float* __restrict__ alpha,
                               const float* __restrict__ beta,
                               float* __restrict__ out) {
    // per compute warp: double-buffered 32x(64+1) tile (pad -> conflict-free)
    __shared__ float sh[CW][2][32][TILE + 1];

    const int wid  = threadIdx.x >> 5;
    const int lane = threadIdx.x & 31;
    const int blockRow = blockIdx.x * (CW * 32);

    if (wid < CW) {
        // ======================= COMPUTE WARP =======================
        const float a = __ldg(alpha);
        const float b = __ldg(beta);
        float w = 1.0f;
        const int bar = 1 + wid;

        PAIR_BAR(bar);                         // tile 0 committed by DMA warp
        for (int t = 0; t < NT; t++) {
            const int p = t & 1;
            #pragma unroll
            for (int j = 0; j < TILE; j++) {   // FROZEN chain, R11/R13 pattern
                const float xv = sh[wid][p][lane][j];
                sh[wid][p][lane][j] = w;
                w = w + a / w - b * xv;
            }
            PAIR_BAR(bar);                     // drains STS; pairs with DMA only
        }
        // DMA warp stores the last tile; compute warps are done.
    } else {
        // ========================= DMA WARP =========================
        const int tr = lane >> 3;   // 0..3
        const int tc = lane & 7;    // 0..7

        const float* xw[CW];
        float*       ow[CW];
        #pragma unroll
        for (int cw = 0; cw < CW; cw++) {
            xw[cw] = x   + (size_t)(blockRow + cw * 32) * N_COLS;
            ow[cw] = out + (size_t)(blockRow + cw * 32) * N_COLS;
        }

        // ---- prologue: load tile 0 into buffer 0 for both compute warps ----
        #pragma unroll
        for (int cw = 0; cw < CW; cw++) {
            float4 pf[16];
            #pragma unroll
            for (int g = 0; g < 8; g++)
                #pragma unroll
                for (int h = 0; h < 2; h++)
                    pf[g * 2 + h] = *(const float4*)(xw[cw]
                        + (size_t)(g * 4 + tr) * N_COLS + (tc + 8 * h) * 4);
            #pragma unroll
            for (int g = 0; g < 8; g++) {
                const int r = g * 4 + tr;
                #pragma unroll
                for (int h = 0; h < 2; h++) {
                    const int c = (tc + 8 * h) * 4;
                    sh[cw][0][r][c + 0] = pf[g * 2 + h].x;
                    sh[cw][0][r][c + 1] = pf[g * 2 + h].y;
                    sh[cw][0][r][c + 2] = pf[g * 2 + h].z;
                    sh[cw][0][r][c + 3] = pf[g * 2 + h].w;
                }
            }
        }
        PAIR_BAR(1);
        PAIR_BAR(2);

        // ---- main loop: while compute chains on buffer p=t&1, service q ----
        for (int t = 0; t < NT; t++) {
            const int q = (t & 1) ^ 1;         // free buffer

            #pragma unroll
            for (int cw = 0; cw < CW; cw++) {
                float4 pf[16];
                // issue tile t+1 LDGs first (fly during store phase)
                if (t + 1 < NT) {
                    const int cn = (t + 1) * TILE;
                    #pragma unroll
                    for (int g = 0; g < 8; g++)
                        #pragma unroll
                        for (int h = 0; h < 2; h++)
                            pf[g * 2 + h] = *(const float4*)(xw[cw]
                                + (size_t)(g * 4 + tr) * N_COLS + cn + (tc + 8 * h) * 4);
                }
                // store tile t-1 outputs from buffer q
                if (t > 0) {
                    const int c0 = (t - 1) * TILE;
                    #pragma unroll
                    for (int g = 0; g < 8; g++) {
                        const int r = g * 4 + tr;
                        #pragma unroll
                        for (int h = 0; h < 2; h++) {
                            const int c = (tc + 8 * h) * 4;
                            float4 v;
                            v.x = sh[cw][q][r][c + 0];
                            v.y = sh[cw][q][r][c + 1];
                            v.z = sh[cw][q][r][c + 2];
                            v.w = sh[cw][q][r][c + 3];
                            *(float4*)(ow[cw] + (size_t)r * N_COLS + c0 + c) = v;
                        }
                    }
                }
                // commit tile t+1 inputs into buffer q (after stores read it;
                // same-lane same-address LDS->STS is program-ordered)
                if (t + 1 < NT) {
                    #pragma unroll
                    for (int g = 0; g < 8; g++) {
                        const int r = g * 4 + tr;
                        #pragma unroll
                        for (int h = 0; h < 2; h++) {
                            const int c = (tc + 8 * h) * 4;
                            sh[cw][q][r][c + 0] = pf[g * 2 + h].x;
                            sh[cw][q][r][c + 1] = pf[g * 2 + h].y;
                            sh[cw][q][r][c + 2] = pf[g * 2 + h].z;
                            sh[cw][q][r][c + 3] = pf[g * 2 + h].w;
                        }
                    }
                }
            }
            PAIR_BAR(1);
            PAIR_BAR(2);
        }

        // ---- epilogue: store last tile's outputs (buffer (NT-1)&1 = 1) ----
        {
            const int c0 = (NT - 1) * TILE;
            #pragma unroll
            for (int cw = 0; cw < CW; cw++)
                #pragma unroll
                for (int g = 0; g < 8; g++) {
                    const int r = g * 4 + tr;
                    #pragma unroll
                    for (int h = 0; h < 2; h++) {
                        const int c = (tc + 8 * h) * 4;
                        float4 v;
                        v.x = sh[cw][1][r][c + 0];
                        v.y = sh[cw][1][r][c + 1];
                        v.z = sh[cw][1][r][c + 2];
                        v.w = sh[cw][1][r][c + 3];
                        *(float4*)(ow[cw] + (size_t)r * N_COLS + c0 + c) = v;
                    }
                }
        }
    }
}

extern "C" void kernel_launch(void* const* d_in, const int* in_sizes, int n_in,
                              void* d_out, int out_size) {
    const float* x     = (const float*)d_in[0];
    const float* alpha = (const float*)d_in[1];
    const float* beta  = (const float*)d_in[2];
    float* out         = (float*)d_out;

    const int rows = out_size / N_COLS;                 // 32768
    const int blocks = rows / (CW * 32);                // 512 (exact)

    DDK_77644418777662_kernel<<<blocks, THREADS>>>(x, alpha, beta, out);
}

// round 15
// speedup vs baseline: 1.6038x; 1.6038x over previous
#include <cuda_runtime.h>
#include <cstdint>

// FINAL KERNEL (= Round 13, best measured: 52.5us ncu / 54.0us bench, rel_err 0.0)
//
// Per-row nonlinear scan, w[k+1] = w[k] + a/w[k] - b*x[k], 32768 rows x 1024.
// Wall-time floor = per-row dependent chain: 1024 x ~90cyc (div.rn macro)
// ~= 51.5us; this kernel sits within ~2% of it.
//
// ARITHMETIC (FROZEN): w = w + a / w - b * xv; xv from smem, w to smem --
// bitwise-identical to reference. Experimentally closed lines:
//   rcp.approx (R3: rel_err 2.05 -- chaotic map near w=0)
//   manual Markstein div (R5/R9: bitwise-correct but SLOWER than the macro)
//   altered tail FMUL+FSUB (R8: rel_err 9e-2)
//   in-warp store fusion into the chain (R6/R7: regressed)
//   xv register preload (R10: neutral -- LDS was never on the chain)
//   TILE=128 (R12: I$ blowout, 128-step unrolled body > 32KB L1.5)
//   per-pair named barriers (R14: DMA warp serializes the two chains)
//
// STRUCTURE: warp specialization. Block = 2 compute warps + 1 DMA warp.
// Compute warps run ONLY the 64-step chain per tile + 1 __syncthreads().
// The DMA warp overlaps ALL memory phases (LDG next tile, STG prev outputs,
// STS commit) with the ~5800-cycle chains, on double-buffered 32x65 tiles
// (pad +1 -> conflict-free). 512 blocks x 96 threads, 4 blocks/SM, 1 wave.

#define N_COLS 1024
#define TILE 64
#define NT (N_COLS / TILE)   // 16
#define CW 2                 // compute warps per block
#define THREADS ((CW + 1) * 32)

__global__ __launch_bounds__(THREADS, 4)
void DDK_77644418777662_kernel(const float* __restrict__ x,
                               const float* __restrict__ alpha,
                               const float* __restrict__ beta,
                               float* __restrict__ out) {
    // per compute warp: double-buffered 32x(64+1) tile (pad -> conflict-free)
    __shared__ float sh[CW][2][32][TILE + 1];

    const int wid  = threadIdx.x >> 5;
    const int lane = threadIdx.x & 31;
    const int blockRow = blockIdx.x * (CW * 32);

    if (wid < CW) {
        // ======================= COMPUTE WARP =======================
        const float a = __ldg(alpha);
        const float b = __ldg(beta);
        float w = 1.0f;

        __syncthreads();                       // tile 0 committed by DMA warp
        for (int t = 0; t < NT; t++) {
            const int p = t & 1;
            #pragma unroll
            for (int j = 0; j < TILE; j++) {   // FROZEN chain
                const float xv = sh[wid][p][lane][j];
                sh[wid][p][lane][j] = w;
                w = w + a / w - b * xv;
            }
            __syncthreads();
        }
        // DMA warp stores the last tile; compute warps are done.
    } else {
        // ========================= DMA WARP =========================
        const int tr = lane >> 3;   // 0..3
        const int tc = lane & 7;    // 0..7

        const float* xw[CW];
        float*       ow[CW];
        #pragma unroll
        for (int cw = 0; cw < CW; cw++) {
            xw[cw] = x   + (size_t)(blockRow + cw * 32) * N_COLS;
            ow[cw] = out + (size_t)(blockRow + cw * 32) * N_COLS;
        }

        // ---- prologue: load tile 0 into buffer 0 for both compute warps ----
        #pragma unroll
        for (int cw = 0; cw < CW; cw++) {
            float4 pf[16];
            #pragma unroll
            for (int g = 0; g < 8; g++)
                #pragma unroll
                for (int h = 0; h < 2; h++)
                    pf[g * 2 + h] = *(const float4*)(xw[cw]
                        + (size_t)(g * 4 + tr) * N_COLS + (tc + 8 * h) * 4);
            #pragma unroll
            for (int g = 0; g < 8; g++) {
                const int r = g * 4 + tr;
                #pragma unroll
                for (int h = 0; h < 2; h++) {
                    const int c = (tc + 8 * h) * 4;
                    sh[cw][0][r][c + 0] = pf[g * 2 + h].x;
                    sh[cw][0][r][c + 1] = pf[g * 2 + h].y;
                    sh[cw][0][r][c + 2] = pf[g * 2 + h].z;
                    sh[cw][0][r][c + 3] = pf[g * 2 + h].w;
                }
            }
        }
        __syncthreads();

        // ---- main loop: while compute chains on buffer p=t&1, service q ----
        for (int t = 0; t < NT; t++) {
            const int q = (t & 1) ^ 1;         // free buffer

            #pragma unroll
            for (int cw = 0; cw < CW; cw++) {
                float4 pf[16];
                // issue tile t+1 LDGs first (fly during store phase)
                if (t + 1 < NT) {
                    const int cn = (t + 1) * TILE;
                    #pragma unroll
                    for (int g = 0; g < 8; g++)
                        #pragma unroll
                        for (int h = 0; h < 2; h++)
                            pf[g * 2 + h] = *(const float4*)(xw[cw]
                                + (size_t)(g * 4 + tr) * N_COLS + cn + (tc + 8 * h) * 4);
                }
                // store tile t-1 outputs from buffer q
                if (t > 0) {
                    const int c0 = (t - 1) * TILE;
                    #pragma unroll
                    for (int g = 0; g < 8; g++) {
                        const int r = g * 4 + tr;
                        #pragma unroll
                        for (int h = 0; h < 2; h++) {
                            const int c = (tc + 8 * h) * 4;
                            float4 v;
                            v.x = sh[cw][q][r][c + 0];
                            v.y = sh[cw][q][r][c + 1];
                            v.z = sh[cw][q][r][c + 2];
                            v.w = sh[cw][q][r][c + 3];
                            *(float4*)(ow[cw] + (size_t)r * N_COLS + c0 + c) = v;
                        }
                    }
                }
                // commit tile t+1 inputs into buffer q (after stores read it;
                // same-lane same-address LDS->STS is program-ordered)
                if (t + 1 < NT) {
                    #pragma unroll
                    for (int g = 0; g < 8; g++) {
                        const int r = g * 4 + tr;
                        #pragma unroll
                        for (int h = 0; h < 2; h++) {
                            const int c = (tc + 8 * h) * 4;
                            sh[cw][q][r][c + 0] = pf[g * 2 + h].x;
                            sh[cw][q][r][c + 1] = pf[g * 2 + h].y;
                            sh[cw][q][r][c + 2] = pf[g * 2 + h].z;
                            sh[cw][q][r][c + 3] = pf[g * 2 + h].w;
                        }
                    }
                }
            }
            __syncthreads();
        }

        // ---- epilogue: store last tile's outputs (buffer (NT-1)&1 = 1) ----
        {
            const int c0 = (NT - 1) * TILE;
            #pragma unroll
            for (int cw = 0; cw < CW; cw++)
                #pragma unroll
                for (int g = 0; g < 8; g++) {
                    const int r = g * 4 + tr;
                    #pragma unroll
                    for (int h = 0; h < 2; h++) {
                        const int c = (tc + 8 * h) * 4;
                        float4 v;
                        v.x = sh[cw][1][r][c + 0];
                        v.y = sh[cw][1][r][c + 1];
                        v.z = sh[cw][1][r][c + 2];
                        v.w = sh[cw][1][r][c + 3];
                        *(float4*)(ow[cw] + (size_t)r * N_COLS + c0 + c) = v;
                    }
                }
        }
    }
}

extern "C" void kernel_launch(void* const* d_in, const int* in_sizes, int n_in,
                              void* d_out, int out_size) {
    const float* x     = (const float*)d_in[0];
    const float* alpha = (const float*)d_in[1];
    const float* beta  = (const float*)d_in[2];
    float* out         = (float*)d_out;

    const int rows = out_size / N_COLS;                 // 32768
    const int blocks = rows / (CW * 32);                // 512 (exact)

    DDK_77644418777662_kernel<<<blocks, THREADS>>>(x, alpha, beta, out);
}

// round 16
// speedup vs baseline: 1.6143x; 1.0065x over previous
#include <cuda_runtime.h>
#include <cstdint>

// FINAL KERNEL (Round 13 architecture; best + re-confirmed: 52.45us ncu /
// 54.0-54.1us bench, rel_err 0.0 on two independent runs).
//
// Per-row nonlinear scan, w[k+1] = w[k] + a/w[k] - b*x[k], 32768 rows x 1024.
// Wall-time floor = per-row dependent chain: 1024 x ~90cyc (div.rn macro)
// ~= 51.5us; this kernel sits within ~2% of it. The time axis is not
// parallelizable (nonlinear recurrence); row parallelism is exhausted
// (one thread/row, single wave, 1.7 warps/SMSP).
//
// ARITHMETIC (FROZEN): w = w + a / w - b * xv; xv from smem, w to smem --
// bitwise-identical to reference. Experimentally closed lines:
//   rcp.approx (R3: rel_err 2.05 -- chaotic map near w=0)
//   manual Markstein div (R5/R9: bitwise-correct but SLOWER than the macro)
//   altered tail FMUL+FSUB (R8: rel_err 9e-2)
//   in-warp store fusion into the chain (R6/R7: regressed)
//   xv register preload (R10: neutral -- LDS was never on the chain)
//   TILE=128 (R12: I$ blowout, 128-step unrolled body)
//   per-pair named barriers (R14: DMA warp serializes the two chains)
//
// STRUCTURE: warp specialization. Block = 2 compute warps + 1 DMA warp.
// Compute warps run ONLY the 64-step chain per tile + 1 __syncthreads().
// The DMA warp overlaps ALL memory phases (LDG next tile, STG prev outputs,
// STS commit) with the ~5800-cycle chains, on double-buffered 32x65 tiles
// (pad +1 -> conflict-free). 512 blocks x 96 threads, 4 blocks/SM, 1 wave.

#define N_COLS 1024
#define TILE 64
#define NT (N_COLS / TILE)   // 16
#define CW 2                 // compute warps per block
#define THREADS ((CW + 1) * 32)

__global__ __launch_bounds__(THREADS, 4)
void DDK_77644418777662_kernel(const float* __restrict__ x,
                               const float* __restrict__ alpha,
                               const float* __restrict__ beta,
                               float* __restrict__ out) {
    // per compute warp: double-buffered 32x(64+1) tile (pad -> conflict-free)
    __shared__ float sh[CW][2][32][TILE + 1];

    const int wid  = threadIdx.x >> 5;
    const int lane = threadIdx.x & 31;
    const int blockRow = blockIdx.x * (CW * 32);

    if (wid < CW) {
        // ======================= COMPUTE WARP =======================
        const float a = __ldg(alpha);
        const float b = __ldg(beta);
        float w = 1.0f;

        __syncthreads();                       // tile 0 committed by DMA warp
        for (int t = 0; t < NT; t++) {
            const int p = t & 1;
            #pragma unroll
            for (int j = 0; j < TILE; j++) {   // FROZEN chain
                const float xv = sh[wid][p][lane][j];
                sh[wid][p][lane][j] = w;
                w = w + a / w - b * xv;
            }
            __syncthreads();
        }
        // DMA warp stores the last tile; compute warps are done.
    } else {
        // ========================= DMA WARP =========================
        const int tr = lane >> 3;   // 0..3
        const int tc = lane & 7;    // 0..7

        const float* xw[CW];
        float*       ow[CW];
        #pragma unroll
        for (int cw = 0; cw < CW; cw++) {
            xw[cw] = x   + (size_t)(blockRow + cw * 32) * N_COLS;
            ow[cw] = out + (size_t)(blockRow + cw * 32) * N_COLS;
        }

        // ---- prologue: load tile 0 into buffer 0 for both compute warps ----
        #pragma unroll
        for (int cw = 0; cw < CW; cw++) {
            float4 pf[16];
            #pragma unroll
            for (int g = 0; g < 8; g++)
                #pragma unroll
                for (int h = 0; h < 2; h++)
                    pf[g * 2 + h] = *(const float4*)(xw[cw]
                        + (size_t)(g * 4 + tr) * N_COLS + (tc + 8 * h) * 4);
            #pragma unroll
            for (int g = 0; g < 8; g++) {
                const int r = g * 4 + tr;
                #pragma unroll
                for (int h = 0; h < 2; h++) {
                    const int c = (tc + 8 * h) * 4;
                    sh[cw][0][r][c + 0] = pf[g * 2 + h].x;
                    sh[cw][0][r][c + 1] = pf[g * 2 + h].y;
                    sh[cw][0][r][c + 2] = pf[g * 2 + h].z;
                    sh[cw][0][r][c + 3] = pf[g * 2 + h].w;
                }
            }
        }
        __syncthreads();

        // ---- main loop: while compute chains on buffer p=t&1, service q ----
        for (int t = 0; t < NT; t++) {
            const int q = (t & 1) ^ 1;         // free buffer

            #pragma unroll
            for (int cw = 0; cw < CW; cw++) {
                float4 pf[16];
                // issue tile t+1 LDGs first (fly during store phase)
                if (t + 1 < NT) {
                    const int cn = (t + 1) * TILE;
                    #pragma unroll
                    for (int g = 0; g < 8; g++)
                        #pragma unroll
                        for (int h = 0; h < 2; h++)
                            pf[g * 2 + h] = *(const float4*)(xw[cw]
                                + (size_t)(g * 4 + tr) * N_COLS + cn + (tc + 8 * h) * 4);
                }
                // store tile t-1 outputs from buffer q
                if (t > 0) {
                    const int c0 = (t - 1) * TILE;
                    #pragma unroll
                    for (int g = 0; g < 8; g++) {
                        const int r = g * 4 + tr;
                        #pragma unroll
                        for (int h = 0; h < 2; h++) {
                            const int c = (tc + 8 * h) * 4;
                            float4 v;
                            v.x = sh[cw][q][r][c + 0];
                            v.y = sh[cw][q][r][c + 1];
                            v.z = sh[cw][q][r][c + 2];
                            v.w = sh[cw][q][r][c + 3];
                            *(float4*)(ow[cw] + (size_t)r * N_COLS + c0 + c) = v;
                        }
                    }
                }
                // commit tile t+1 inputs into buffer q (after stores read it;
                // same-lane same-address LDS->STS is program-ordered)
                if (t + 1 < NT) {
                    #pragma unroll
                    for (int g = 0; g < 8; g++) {
                        const int r = g * 4 + tr;
                        #pragma unroll
                        for (int h = 0; h < 2; h++) {
                            const int c = (tc + 8 * h) * 4;
                            sh[cw][q][r][c + 0] = pf[g * 2 + h].x;
                            sh[cw][q][r][c + 1] = pf[g * 2 + h].y;
                            sh[cw][q][r][c + 2] = pf[g * 2 + h].z;
                            sh[cw][q][r][c + 3] = pf[g * 2 + h].w;
                        }
                    }
                }
            }
            __syncthreads();
        }

        // ---- epilogue: store last tile's outputs (buffer (NT-1)&1 = 1) ----
        {
            const int c0 = (NT - 1) * TILE;
            #pragma unroll
            for (int cw = 0; cw < CW; cw++)
                #pragma unroll
                for (int g = 0; g < 8; g++) {
                    const int r = g * 4 + tr;
                    #pragma unroll
                    for (int h = 0; h < 2; h++) {
                        const int c = (tc + 8 * h) * 4;
                        float4 v;
                        v.x = sh[cw][1][r][c + 0];
                        v.y = sh[cw][1][r][c + 1];
                        v.z = sh[cw][1][r][c + 2];
                        v.w = sh[cw][1][r][c + 3];
                        *(float4*)(ow[cw] + (size_t)r * N_COLS + c0 + c) = v;
                    }
                }
        }
    }
}

extern "C" void kernel_launch(void* const* d_in, const int* in_sizes, int n_in,
                              void* d_out, int out_size) {
    const float* x     = (const float*)d_in[0];
    const float* alpha = (const float*)d_in[1];
    const float* beta  = (const float*)d_in[2];
    float* out         = (float*)d_out;

    const int rows = out_size / N_COLS;                 // 32768
    const int blocks = rows / (CW * 32);                // 512 (exact)

    DDK_77644418777662_kernel<<<blocks, THREADS>>>(x, alpha, beta, out);
}